// round 12
// baseline (speedup 1.0000x reference)
#include <cuda_runtime.h>
#include <cstddef>
#include <cstdint>

// ---------------------------------------------------------------------------
// Sparse 3D UNet forward. All neighbor tables precomputed host-side (inputs).
// Each conv: out[i,:] = sum_k (feat[nbr[i,k],:] or 0) @ W[k]  -> *scale+bias
//            -> (+residual) -> relu -> (+pair-reduce of cat)
//
// R11: barrier-free mainloop. Each warp gathers/double-buffers its OWN rows
// (cp.async + __syncwarp only); weights read via uniform L1-cached __ldg
// (no weight smem). FFMA2 packed math + XOR-swizzled activation smem kept.
// ---------------------------------------------------------------------------

#define NMAX (1 << 20)

__device__ float g_x1 [(size_t)NMAX * 32];
__device__ float g_x2 [(size_t)NMAX * 32];
__device__ float g_x3 [(size_t)NMAX * 64];
__device__ float g_x4 [(size_t)NMAX * 64];
__device__ float g_a  [(size_t)NMAX * 64];
__device__ float g_b  [(size_t)NMAX * 64];
__device__ float g_t  [(size_t)NMAX * 64];
__device__ float g_cat[(size_t)NMAX * 128];

// ---- cp.async helpers ------------------------------------------------------
__device__ __forceinline__ void cp_async16(uint32_t dst, const void* src, bool full)
{
    int sz = full ? 16 : 0;
    asm volatile("cp.async.ca.shared.global [%0], [%1], 16, %2;"
                 :: "r"(dst), "l"(src), "r"(sz));
}
__device__ __forceinline__ void cp_commit()
{
    asm volatile("cp.async.commit_group;");
}
template <int N>
__device__ __forceinline__ void cp_wait()
{
    asm volatile("cp.async.wait_group %0;" :: "n"(N));
}

// ---- f32x2 packed math -----------------------------------------------------
__device__ __forceinline__ unsigned long long dup2(float a)
{
    unsigned long long r;
    asm("mov.b64 %0, {%1, %1};" : "=l"(r) : "f"(a));
    return r;
}
__device__ __forceinline__ void ffma2(unsigned long long& d,
                                      unsigned long long a, unsigned long long b)
{
    asm("fma.rn.f32x2 %0, %1, %2, %0;" : "+l"(d) : "l"(a), "l"(b));
}
__device__ __forceinline__ float2 unpk2(unsigned long long v)
{
    float2 f;
    asm("mov.b64 {%0, %1}, %2;" : "=f"(f.x), "=f"(f.y) : "l"(v));
    return f;
}

// ---------------------------------------------------------------------------
// conv kernel: block = (8, BY/ROWPT). Each thread: ROWPT rows x COUT/8 couts.
// Each warp owns 4*ROWPT rows; gathers them itself; no block barriers.
// Dynamic smem: in_s[2][BY*CCH] (XOR-swizzled). Weights via __ldg.
// ---------------------------------------------------------------------------
template <int CIN, int COUT, int BY, int ROWPT>
__global__ void __launch_bounds__(8 * BY / ROWPT)
conv_kernel(const float* __restrict__ in,       // [n_in, CIN]
            const int*   __restrict__ nbr,      // [n_out, 27]
            int n_out,
            const float* __restrict__ W,        // [27, CIN, COUT]
            const float* __restrict__ sb,       // scale[COUT], bias[COUT]
            const float* __restrict__ res_pre,  // nullable [n_out, COUT]
            const float* __restrict__ red_post, // nullable [n_out, 2*COUT]
            float* __restrict__ out)            // [n_out, COUT]
{
    constexpr int BX    = 8;
    constexpr int VEC   = COUT / BX;               // 4 or 8
    constexpr int CCH   = (CIN <= 64) ? CIN : 64;  // CIN chunk
    constexpr int NSTG  = CIN / CCH;               // chunks per k
    constexpr int S     = 27 * NSTG;               // pipeline stages
    constexpr int C4    = CCH / 4;                 // 16B chunks per row
    constexpr int SWM   = (C4 - 1 < 7) ? (C4 - 1) : 7;  // swizzle mask
    constexpr int INSZ  = BY * CCH;                // floats per input buf
    constexpr int WROWS = 4 * ROWPT;               // rows owned per warp

    extern __shared__ float smem[];   // in_s[2][INSZ]

    const int tx   = threadIdx.x;
    const int ty   = threadIdx.y;
    const int tid  = ty * BX + tx;
    const int wid  = tid >> 5;
    const int lid  = tid & 31;
    const int row0 = blockIdx.x * BY;
    const int tysw = ty & SWM;

    const uint32_t in_u32 = (uint32_t)__cvta_generic_to_shared(smem);

    unsigned long long acc2[ROWPT][VEC / 2];
#pragma unroll
    for (int i = 0; i < ROWPT; i++)
#pragma unroll
        for (int j = 0; j < VEC / 2; j++) acc2[i][j] = 0ull;

    // ---- per-warp stage issue: gather this warp's rows into buffer s%2 ----
    auto issue = [&](int s) {
        const int k  = s / NSTG;
        const int cc = (s - k * NSTG) * CCH;
        const uint32_t ind = in_u32 + (s & 1) * INSZ * 4;
#pragma unroll
        for (int i = lid; i < WROWS * C4; i += 32) {
            int rl = i / C4;
            int c4 = i - rl * C4;
            int r  = wid * WROWS + rl;
            int sw = c4 ^ ((r / ROWPT) & SWM);
            int gr = row0 + r;
            int g  = (gr < n_out) ? __ldg(nbr + (size_t)gr * 27 + k) : -1;
            const float* src = in + ((size_t)(g < 0 ? 0 : g) * CIN + cc + c4 * 4);
            cp_async16(ind + (r * CCH + sw * 4) * 4, src, g >= 0);
        }
        cp_commit();
    };

    issue(0);

    for (int s = 0; s < S; s++) {
        if (s + 1 < S) { issue(s + 1); cp_wait<1>(); }
        else          { cp_wait<0>(); }
        __syncwarp();

        const int k  = s / NSTG;
        const int cc = (s - k * NSTG) * CCH;
        const float* ib0 = smem + (s & 1) * INSZ + ty * ROWPT * CCH;
        const float* wk0 = W + ((size_t)k * CIN + cc) * COUT + tx * VEC;

#pragma unroll
        for (int cch = 0; cch < C4; cch++) {
            const int c  = cch * 4;
            const int sw = (cch ^ tysw) * 4;
            float4 a4[ROWPT];
#pragma unroll
            for (int i = 0; i < ROWPT; i++)
                a4[i] = *reinterpret_cast<const float4*>(ib0 + i * CCH + sw);
#pragma unroll
            for (int c2 = 0; c2 < 4; c2++) {
                unsigned long long ad[ROWPT];
#pragma unroll
                for (int i = 0; i < ROWPT; i++)
                    ad[i] = dup2(c2 == 0 ? a4[i].x :
                                 c2 == 1 ? a4[i].y :
                                 c2 == 2 ? a4[i].z : a4[i].w);
#pragma unroll
                for (int j = 0; j < VEC / 4; j++) {
                    // uniform-per-(tx) coalesced 128B line; L1-resident weights
                    float4 wf = __ldg(reinterpret_cast<const float4*>(
                        wk0 + (c + c2) * COUT + j * 4));
                    unsigned long long wlo, whi;
                    asm("mov.b64 %0, {%1, %2};" : "=l"(wlo) : "f"(wf.x), "f"(wf.y));
                    asm("mov.b64 %0, {%1, %2};" : "=l"(whi) : "f"(wf.z), "f"(wf.w));
#pragma unroll
                    for (int i = 0; i < ROWPT; i++) {
                        ffma2(acc2[i][j * 2 + 0], ad[i], wlo);
                        ffma2(acc2[i][j * 2 + 1], ad[i], whi);
                    }
                }
            }
        }
        __syncwarp();   // warp done reading buf s&1 before issue(s+2) refills
    }

#pragma unroll
    for (int i = 0; i < ROWPT; i++) {
        const int row = row0 + ty * ROWPT + i;
        if (row >= n_out) continue;
#pragma unroll
        for (int j = 0; j < VEC / 4; j++) {
            const int co = tx * VEC + j * 4;
            float2 p0 = unpk2(acc2[i][j * 2 + 0]);
            float2 p1 = unpk2(acc2[i][j * 2 + 1]);
            float4 sc  = *reinterpret_cast<const float4*>(sb + co);
            float4 bi4 = *reinterpret_cast<const float4*>(sb + COUT + co);
            float v0 = p0.x * sc.x + bi4.x;
            float v1 = p0.y * sc.y + bi4.y;
            float v2 = p1.x * sc.z + bi4.z;
            float v3 = p1.y * sc.w + bi4.w;
            if (res_pre) {
                float4 rp = *reinterpret_cast<const float4*>(
                    res_pre + (size_t)row * COUT + co);
                v0 += rp.x; v1 += rp.y; v2 += rp.z; v3 += rp.w;
            }
            v0 = fmaxf(v0, 0.f);
            v1 = fmaxf(v1, 0.f);
            v2 = fmaxf(v2, 0.f);
            v3 = fmaxf(v3, 0.f);
            if (red_post) {
                const float* rp = red_post + (size_t)row * 2 * COUT + 2 * co;
                v0 += rp[0] + rp[1];
                v1 += rp[2] + rp[3];
                v2 += rp[4] + rp[5];
                v3 += rp[6] + rp[7];
            }
            float4 o; o.x = v0; o.y = v1; o.z = v2; o.w = v3;
            *reinterpret_cast<float4*>(out + (size_t)row * COUT + co) = o;
        }
    }
}

// concat along channels
__global__ void concat_kernel(const float* __restrict__ a, const float* __restrict__ b,
                              int n, int C4, float* __restrict__ out)
{
    int i = blockIdx.x * blockDim.x + threadIdx.x;
    int total = n * C4;
    if (i >= total) return;
    int r = i / C4, c = i - r * C4;
    const float4* a4 = reinterpret_cast<const float4*>(a);
    const float4* b4 = reinterpret_cast<const float4*>(b);
    float4*       o4 = reinterpret_cast<float4*>(out);
    o4[(size_t)r * 2 * C4 + c]      = a4[i];
    o4[(size_t)r * 2 * C4 + C4 + c] = b4[i];
}

// ---------------------------------------------------------------------------
template <int CIN, int COUT, int BY, int ROWPT>
static inline void conv(const float* in, const int* nbr, int n,
                        const float* W, const float* sb,
                        const float* res, const float* red, float* out)
{
    if (n <= 0) return;
    constexpr int CCH  = (CIN <= 64) ? CIN : 64;
    constexpr int SMEM = 2 * BY * CCH * 4;
    static bool attr_done = false;
    if (!attr_done) {
        cudaFuncSetAttribute(conv_kernel<CIN, COUT, BY, ROWPT>,
                             cudaFuncAttributeMaxDynamicSharedMemorySize, SMEM);
        attr_done = true;
    }
    dim3 blk(8, BY / ROWPT);
    conv_kernel<CIN, COUT, BY, ROWPT><<<(n + BY - 1) / BY, blk, SMEM>>>(
        in, nbr, n, W, sb, res, red, out);
}

static inline void concat(const float* a, const float* b, int n, int C, float* out)
{
    if (n <= 0) return;
    int total = n * (C / 4);
    concat_kernel<<<(total + 255) / 256, 256>>>(a, b, n, C / 4, out);
}

extern "C" void kernel_launch(void* const* d_in, const int* in_sizes, int n_in,
                              void* d_out, int out_size)
{
    (void)n_in; (void)out_size;
    const float* vf     = (const float*)d_in[0];
    const float* Win    = (const float*)d_in[1];
    const float* W32    = (const float*)d_in[2];
    const float* W64    = (const float*)d_in[3];
    const float* Wd3    = (const float*)d_in[4];
    const float* W6432  = (const float*)d_in[5];
    const float* W12864 = (const float*)d_in[6];
    const float* bn32   = (const float*)d_in[7];
    const float* bn64   = (const float*)d_in[8];
    const int* nbr1  = (const int*)d_in[9];
    const int* nbr2  = (const int*)d_in[10];
    const int* nbr3  = (const int*)d_in[11];
    const int* nbr4  = (const int*)d_in[12];
    const int* nbrd2 = (const int*)d_in[13];
    const int* nbrd3 = (const int*)d_in[14];
    const int* nbrd4 = (const int*)d_in[15];
    const int* nbri4 = (const int*)d_in[16];
    const int* nbri3 = (const int*)d_in[17];
    const int* nbri2 = (const int*)d_in[18];

    const int N1 = in_sizes[0] / 4;
    const int N2 = in_sizes[10] / 27;
    const int N3 = in_sizes[11] / 27;
    const int N4 = in_sizes[12] / 27;

    float *X1, *X2, *X3, *X4, *A, *B, *T, *CAT;
    cudaGetSymbolAddress((void**)&X1,  g_x1);
    cudaGetSymbolAddress((void**)&X2,  g_x2);
    cudaGetSymbolAddress((void**)&X3,  g_x3);
    cudaGetSymbolAddress((void**)&X4,  g_x4);
    cudaGetSymbolAddress((void**)&A,   g_a);
    cudaGetSymbolAddress((void**)&B,   g_b);
    cudaGetSymbolAddress((void**)&T,   g_t);
    cudaGetSymbolAddress((void**)&CAT, g_cat);
    float* OUT = (float*)d_out;

    const int S32   = 27 * 32 * 32;
    const int S64   = 27 * 64 * 64;
    const int S6432 = 27 * 64 * 32;
    const int S1286 = 27 * 128 * 64;
#define BN32(i) (bn32 + (i) * 64)
#define BN64(i) (bn64 + (i) * 128)

    // ---- encoder ----
    conv<4,  32, 128, 8>(vf, nbr1,  N1, Win,           BN32(0), 0, 0, A);
    conv<32, 32, 128, 8>(A,  nbr1,  N1, W32 + 0 * S32, BN32(1), 0, 0, X1);  // x1
    conv<32, 32, 128, 8>(X1, nbrd2, N2, W32 + 1 * S32, BN32(2), 0, 0, A);
    conv<32, 32, 128, 8>(A,  nbr2,  N2, W32 + 2 * S32, BN32(3), 0, 0, B);
    conv<32, 32, 128, 8>(B,  nbr2,  N2, W32 + 3 * S32, BN32(4), 0, 0, X2);  // x2
    conv<32, 64, 64, 4>(X2, nbrd3, N3, Wd3,           BN64(0), 0, 0, A);
    conv<64, 64, 64, 4>(A,  nbr3,  N3, W64 + 0 * S64, BN64(1), 0, 0, B);
    conv<64, 64, 64, 4>(B,  nbr3,  N3, W64 + 1 * S64, BN64(2), 0, 0, X3);   // x3
    conv<64, 64, 64, 4>(X3, nbrd4, N4, W64 + 2 * S64, BN64(3), 0, 0, A);
    conv<64, 64, 64, 4>(A,  nbr4,  N4, W64 + 3 * S64, BN64(4), 0, 0, B);
    conv<64, 64, 64, 4>(B,  nbr4,  N4, W64 + 4 * S64, BN64(5), 0, 0, X4);   // x4

    // ---- level 4 ----
    conv<64, 64, 64, 4>(X4, nbr4, N4, W64 + 5 * S64, BN64(6), 0, 0, A);
    conv<64, 64, 64, 4>(A,  nbr4, N4, W64 + 6 * S64, BN64(7), X4, 0, T);    // t
    concat(X4, T, N4, 64, CAT);
    conv<128, 64, 64, 4>(CAT, nbr4, N4, W12864 + 0 * S1286, BN64(11), 0, CAT, A);

    // ---- up to level 3 ----
    conv<64, 64, 64, 4>(A,  nbri4, N3, W64 + 7 * S64, BN64(8), 0, 0, B);    // xu4
    conv<64, 64, 64, 4>(X3, nbr3,  N3, W64 + 8 * S64, BN64(9), 0, 0, A);
    conv<64, 64, 64, 4>(A,  nbr3,  N3, W64 + 9 * S64, BN64(10), X3, 0, T);  // t3
    concat(B, T, N3, 64, CAT);
    conv<128, 64, 64, 4>(CAT, nbr3, N3, W12864 + 1 * S1286, BN64(12), 0, CAT, A);

    // ---- up to level 2 ----
    conv<64, 32, 128, 8>(A,  nbri3, N2, W6432 + 0 * S6432, BN32(11), 0, 0, B);  // xu3
    conv<32, 32, 128, 8>(X2, nbr2,  N2, W32 + 4 * S32, BN32(5), 0, 0, A);
    conv<32, 32, 128, 8>(A,  nbr2,  N2, W32 + 5 * S32, BN32(6), X2, 0, T);  // t2
    concat(B, T, N2, 32, CAT);
    conv<64, 32, 128, 8>(CAT, nbr2, N2, W6432 + 1 * S6432, BN32(12), 0, CAT, A);

    // ---- up to level 1 ----
    conv<32, 32, 128, 8>(A,  nbri2, N1, W32 + 6 * S32, BN32(7), 0, 0, B);   // xu2
    conv<32, 32, 128, 8>(X1, nbr1,  N1, W32 + 7 * S32, BN32(8), 0, 0, A);
    conv<32, 32, 128, 8>(A,  nbr1,  N1, W32 + 8 * S32, BN32(9), X1, 0, T);  // t1
    concat(B, T, N1, 32, CAT);
    conv<64, 32, 128, 8>(CAT, nbr1, N1, W6432 + 2 * S6432, BN32(13), 0, CAT, A);

    // ---- head ----
    conv<32, 32, 128, 8>(A, nbr1, N1, W32 + 9 * S32, BN32(10), 0, 0, OUT);

#undef BN32
#undef BN64
}

// round 14
// speedup vs baseline: 1.3813x; 1.3813x over previous
#include <cuda_runtime.h>
#include <cstddef>
#include <cstdint>

// ---------------------------------------------------------------------------
// Sparse 3D UNet forward. All neighbor tables precomputed host-side (inputs).
// Each conv: out[i,:] = sum_k (feat[nbr[i,k],:] or 0) @ W[k]  -> *scale+bias
//            -> (+residual) -> relu -> (+pair-reduce of cat)
//
// R12: R7 structure (block cp.async double-buffer, weights in smem, XOR
// swizzle) + FFMA2 packed math with reshaped tiles (VEC=8) so the packed
// path actually reduces issue slots. No LDG in mainloop (R11 lesson).
// ---------------------------------------------------------------------------

#define NMAX (1 << 20)

__device__ float g_x1 [(size_t)NMAX * 32];
__device__ float g_x2 [(size_t)NMAX * 32];
__device__ float g_x3 [(size_t)NMAX * 64];
__device__ float g_x4 [(size_t)NMAX * 64];
__device__ float g_a  [(size_t)NMAX * 64];
__device__ float g_b  [(size_t)NMAX * 64];
__device__ float g_t  [(size_t)NMAX * 64];
__device__ float g_cat[(size_t)NMAX * 128];

// ---- cp.async helpers ------------------------------------------------------
__device__ __forceinline__ void cp_async16(uint32_t dst, const void* src, bool full)
{
    int sz = full ? 16 : 0;
    asm volatile("cp.async.ca.shared.global [%0], [%1], 16, %2;"
                 :: "r"(dst), "l"(src), "r"(sz));
}
__device__ __forceinline__ void cp_commit()
{
    asm volatile("cp.async.commit_group;");
}
template <int N>
__device__ __forceinline__ void cp_wait()
{
    asm volatile("cp.async.wait_group %0;" :: "n"(N));
}

// ---- f32x2 packed math -----------------------------------------------------
__device__ __forceinline__ unsigned long long dup2(float a)
{
    unsigned long long r;
    asm("mov.b64 %0, {%1, %1};" : "=l"(r) : "f"(a));
    return r;
}
__device__ __forceinline__ void ffma2(unsigned long long& d,
                                      unsigned long long a, unsigned long long b)
{
    asm("fma.rn.f32x2 %0, %1, %2, %0;" : "+l"(d) : "l"(a), "l"(b));
}
__device__ __forceinline__ float2 unpk2(unsigned long long v)
{
    float2 f;
    asm("mov.b64 {%0, %1}, %2;" : "=f"(f.x), "=f"(f.y) : "l"(v));
    return f;
}

// ---------------------------------------------------------------------------
// conv kernel: block = (BX, BY/ROWPT). Each thread: ROWPT rows x VEC couts
// (VEC = COUT/BX). Dynamic smem: [ w_s[2][CCH*COUT] | in_s[2][BY*CCH] ].
// ---------------------------------------------------------------------------
template <int CIN, int COUT, int BX, int BY, int ROWPT>
__global__ void __launch_bounds__(BX * BY / ROWPT)
conv_kernel(const float* __restrict__ in,       // [n_in, CIN]
            const int*   __restrict__ nbr,      // [n_out, 27]
            int n_out,
            const float* __restrict__ W,        // [27, CIN, COUT]
            const float* __restrict__ sb,       // scale[COUT], bias[COUT]
            const float* __restrict__ res_pre,  // nullable [n_out, COUT]
            const float* __restrict__ red_post, // nullable [n_out, 2*COUT]
            float* __restrict__ out)            // [n_out, COUT]
{
    constexpr int VEC   = COUT / BX;               // 4 or 8
    constexpr int NT    = BX * (BY / ROWPT);
    constexpr int CCH   = (CIN <= 64) ? CIN : 64;  // CIN chunk
    constexpr int NSTG  = CIN / CCH;               // chunks per k
    constexpr int S     = 27 * NSTG;               // pipeline stages
    constexpr int C4    = CCH / 4;                 // 16B chunks per row
    constexpr int SWM   = (C4 - 1 < 7) ? (C4 - 1) : 7;  // swizzle mask
    constexpr int WSZ   = CCH * COUT;              // floats per weight buf
    constexpr int INSZ  = BY * CCH;                // floats per input buf

    extern __shared__ float smem[];
    float* w_s  = smem;                  // [2][WSZ]
    float* in_s = smem + 2 * WSZ;        // [2][INSZ]

    const int tx   = threadIdx.x;
    const int ty   = threadIdx.y;
    const int tid  = ty * BX + tx;
    const int row0 = blockIdx.x * BY;
    const int tysw = ty & SWM;

    const uint32_t smem_u32 = (uint32_t)__cvta_generic_to_shared(smem);
    const uint32_t w_u32    = smem_u32;
    const uint32_t in_u32   = smem_u32 + 2 * WSZ * 4;

    unsigned long long acc2[ROWPT][VEC / 2];
#pragma unroll
    for (int i = 0; i < ROWPT; i++)
#pragma unroll
        for (int j = 0; j < VEC / 2; j++) acc2[i][j] = 0ull;

    auto issue = [&](int s) {
        const int k  = s / NSTG;
        const int cc = (s - k * NSTG) * CCH;
        const int bi = s & 1;
        {
            const float* Wk = W + ((size_t)k * CIN + cc) * COUT;
            const uint32_t wd = w_u32 + bi * WSZ * 4;
#pragma unroll
            for (int i = tid; i < WSZ / 4; i += NT)
                cp_async16(wd + i * 16, Wk + i * 4, true);
        }
        {
            const uint32_t ind = in_u32 + bi * INSZ * 4;
            for (int i = tid; i < BY * C4; i += NT) {
                int r  = i / C4;
                int c4 = i - r * C4;
                int sw = c4 ^ ((r / ROWPT) & SWM);
                int gr = row0 + r;
                int g  = (gr < n_out) ? __ldg(nbr + (size_t)gr * 27 + k) : -1;
                const float* src = in + ((size_t)(g < 0 ? 0 : g) * CIN + cc + c4 * 4);
                cp_async16(ind + (r * CCH + sw * 4) * 4, src, g >= 0);
            }
        }
        cp_commit();
    };

    issue(0);

    for (int s = 0; s < S; s++) {
        if (s + 1 < S) { issue(s + 1); cp_wait<1>(); }
        else          { cp_wait<0>(); }
        __syncthreads();

        const int bi = s & 1;
        const float* wb0 = w_s  + bi * WSZ + tx * VEC;
        const float* ib0 = in_s + bi * INSZ + ty * ROWPT * CCH;

#pragma unroll
        for (int cch = 0; cch < C4; cch++) {
            const int c  = cch * 4;
            const int sw = (cch ^ tysw) * 4;
            float4 a4[ROWPT];
#pragma unroll
            for (int i = 0; i < ROWPT; i++)
                a4[i] = *reinterpret_cast<const float4*>(ib0 + i * CCH + sw);
#pragma unroll
            for (int c2 = 0; c2 < 4; c2++) {
                unsigned long long ad[ROWPT];
#pragma unroll
                for (int i = 0; i < ROWPT; i++)
                    ad[i] = dup2(c2 == 0 ? a4[i].x :
                                 c2 == 1 ? a4[i].y :
                                 c2 == 2 ? a4[i].z : a4[i].w);
#pragma unroll
                for (int j = 0; j < VEC / 4; j++) {
                    ulonglong2 wv = *reinterpret_cast<const ulonglong2*>(
                        wb0 + (c + c2) * COUT + j * 4);
#pragma unroll
                    for (int i = 0; i < ROWPT; i++) {
                        ffma2(acc2[i][j * 2 + 0], ad[i], wv.x);
                        ffma2(acc2[i][j * 2 + 1], ad[i], wv.y);
                    }
                }
            }
        }
        __syncthreads();
    }

#pragma unroll
    for (int i = 0; i < ROWPT; i++) {
        const int row = row0 + ty * ROWPT + i;
        if (row >= n_out) continue;
#pragma unroll
        for (int j = 0; j < VEC / 4; j++) {
            const int co = tx * VEC + j * 4;
            float2 p0 = unpk2(acc2[i][j * 2 + 0]);
            float2 p1 = unpk2(acc2[i][j * 2 + 1]);
            float4 sc  = *reinterpret_cast<const float4*>(sb + co);
            float4 bi4 = *reinterpret_cast<const float4*>(sb + COUT + co);
            float v0 = p0.x * sc.x + bi4.x;
            float v1 = p0.y * sc.y + bi4.y;
            float v2 = p1.x * sc.z + bi4.z;
            float v3 = p1.y * sc.w + bi4.w;
            if (res_pre) {
                float4 rp = *reinterpret_cast<const float4*>(
                    res_pre + (size_t)row * COUT + co);
                v0 += rp.x; v1 += rp.y; v2 += rp.z; v3 += rp.w;
            }
            v0 = fmaxf(v0, 0.f);
            v1 = fmaxf(v1, 0.f);
            v2 = fmaxf(v2, 0.f);
            v3 = fmaxf(v3, 0.f);
            if (red_post) {
                const float* rp = red_post + (size_t)row * 2 * COUT + 2 * co;
                v0 += rp[0] + rp[1];
                v1 += rp[2] + rp[3];
                v2 += rp[4] + rp[5];
                v3 += rp[6] + rp[7];
            }
            float4 o; o.x = v0; o.y = v1; o.z = v2; o.w = v3;
            *reinterpret_cast<float4*>(out + (size_t)row * COUT + co) = o;
        }
    }
}

// concat along channels
__global__ void concat_kernel(const float* __restrict__ a, const float* __restrict__ b,
                              int n, int C4, float* __restrict__ out)
{
    int i = blockIdx.x * blockDim.x + threadIdx.x;
    int total = n * C4;
    if (i >= total) return;
    int r = i / C4, c = i - r * C4;
    const float4* a4 = reinterpret_cast<const float4*>(a);
    const float4* b4 = reinterpret_cast<const float4*>(b);
    float4*       o4 = reinterpret_cast<float4*>(out);
    o4[(size_t)r * 2 * C4 + c]      = a4[i];
    o4[(size_t)r * 2 * C4 + C4 + c] = b4[i];
}

// ---------------------------------------------------------------------------
template <int CIN, int COUT, int BX, int BY, int ROWPT>
static inline void conv(const float* in, const int* nbr, int n,
                        const float* W, const float* sb,
                        const float* res, const float* red, float* out)
{
    if (n <= 0) return;
    constexpr int CCH  = (CIN <= 64) ? CIN : 64;
    constexpr int SMEM = 2 * (CCH * COUT + BY * CCH) * 4;
    static bool attr_done = false;
    if (!attr_done) {
        cudaFuncSetAttribute(conv_kernel<CIN, COUT, BX, BY, ROWPT>,
                             cudaFuncAttributeMaxDynamicSharedMemorySize, SMEM);
        attr_done = true;
    }
    dim3 blk(BX, BY / ROWPT);
    conv_kernel<CIN, COUT, BX, BY, ROWPT><<<(n + BY - 1) / BY, blk, SMEM>>>(
        in, nbr, n, W, sb, res, red, out);
}

static inline void concat(const float* a, const float* b, int n, int C, float* out)
{
    if (n <= 0) return;
    int total = n * (C / 4);
    concat_kernel<<<(total + 255) / 256, 256>>>(a, b, n, C / 4, out);
}

extern "C" void kernel_launch(void* const* d_in, const int* in_sizes, int n_in,
                              void* d_out, int out_size)
{
    (void)n_in; (void)out_size;
    const float* vf     = (const float*)d_in[0];
    const float* Win    = (const float*)d_in[1];
    const float* W32    = (const float*)d_in[2];
    const float* W64    = (const float*)d_in[3];
    const float* Wd3    = (const float*)d_in[4];
    const float* W6432  = (const float*)d_in[5];
    const float* W12864 = (const float*)d_in[6];
    const float* bn32   = (const float*)d_in[7];
    const float* bn64   = (const float*)d_in[8];
    const int* nbr1  = (const int*)d_in[9];
    const int* nbr2  = (const int*)d_in[10];
    const int* nbr3  = (const int*)d_in[11];
    const int* nbr4  = (const int*)d_in[12];
    const int* nbrd2 = (const int*)d_in[13];
    const int* nbrd3 = (const int*)d_in[14];
    const int* nbrd4 = (const int*)d_in[15];
    const int* nbri4 = (const int*)d_in[16];
    const int* nbri3 = (const int*)d_in[17];
    const int* nbri2 = (const int*)d_in[18];

    const int N1 = in_sizes[0] / 4;
    const int N2 = in_sizes[10] / 27;
    const int N3 = in_sizes[11] / 27;
    const int N4 = in_sizes[12] / 27;

    float *X1, *X2, *X3, *X4, *A, *B, *T, *CAT;
    cudaGetSymbolAddress((void**)&X1,  g_x1);
    cudaGetSymbolAddress((void**)&X2,  g_x2);
    cudaGetSymbolAddress((void**)&X3,  g_x3);
    cudaGetSymbolAddress((void**)&X4,  g_x4);
    cudaGetSymbolAddress((void**)&A,   g_a);
    cudaGetSymbolAddress((void**)&B,   g_b);
    cudaGetSymbolAddress((void**)&T,   g_t);
    cudaGetSymbolAddress((void**)&CAT, g_cat);
    float* OUT = (float*)d_out;

    const int S32   = 27 * 32 * 32;
    const int S64   = 27 * 64 * 64;
    const int S6432 = 27 * 64 * 32;
    const int S1286 = 27 * 128 * 64;
#define BN32(i) (bn32 + (i) * 64)
#define BN64(i) (bn64 + (i) * 128)

    // ---- encoder ----
    conv<4,  32, 4, 128, 4>(vf, nbr1,  N1, Win,           BN32(0), 0, 0, A);
    conv<32, 32, 4, 128, 4>(A,  nbr1,  N1, W32 + 0 * S32, BN32(1), 0, 0, X1);  // x1
    conv<32, 32, 4, 128, 4>(X1, nbrd2, N2, W32 + 1 * S32, BN32(2), 0, 0, A);
    conv<32, 32, 4, 128, 4>(A,  nbr2,  N2, W32 + 2 * S32, BN32(3), 0, 0, B);
    conv<32, 32, 4, 128, 4>(B,  nbr2,  N2, W32 + 3 * S32, BN32(4), 0, 0, X2);  // x2
    conv<32, 64, 8, 64, 4>(X2, nbrd3, N3, Wd3,           BN64(0), 0, 0, A);
    conv<64, 64, 8, 64, 4>(A,  nbr3,  N3, W64 + 0 * S64, BN64(1), 0, 0, B);
    conv<64, 64, 8, 64, 4>(B,  nbr3,  N3, W64 + 1 * S64, BN64(2), 0, 0, X3);   // x3
    conv<64, 64, 8, 64, 4>(X3, nbrd4, N4, W64 + 2 * S64, BN64(3), 0, 0, A);
    conv<64, 64, 8, 64, 4>(A,  nbr4,  N4, W64 + 3 * S64, BN64(4), 0, 0, B);
    conv<64, 64, 8, 64, 4>(B,  nbr4,  N4, W64 + 4 * S64, BN64(5), 0, 0, X4);   // x4

    // ---- level 4 ----
    conv<64, 64, 8, 64, 4>(X4, nbr4, N4, W64 + 5 * S64, BN64(6), 0, 0, A);
    conv<64, 64, 8, 64, 4>(A,  nbr4, N4, W64 + 6 * S64, BN64(7), X4, 0, T);    // t
    concat(X4, T, N4, 64, CAT);
    conv<128, 64, 8, 64, 4>(CAT, nbr4, N4, W12864 + 0 * S1286, BN64(11), 0, CAT, A);

    // ---- up to level 3 ----
    conv<64, 64, 8, 64, 4>(A,  nbri4, N3, W64 + 7 * S64, BN64(8), 0, 0, B);    // xu4
    conv<64, 64, 8, 64, 4>(X3, nbr3,  N3, W64 + 8 * S64, BN64(9), 0, 0, A);
    conv<64, 64, 8, 64, 4>(A,  nbr3,  N3, W64 + 9 * S64, BN64(10), X3, 0, T);  // t3
    concat(B, T, N3, 64, CAT);
    conv<128, 64, 8, 64, 4>(CAT, nbr3, N3, W12864 + 1 * S1286, BN64(12), 0, CAT, A);

    // ---- up to level 2 ----
    conv<64, 32, 8, 64, 4>(A,  nbri3, N2, W6432 + 0 * S6432, BN32(11), 0, 0, B);  // xu3
    conv<32, 32, 4, 128, 4>(X2, nbr2,  N2, W32 + 4 * S32, BN32(5), 0, 0, A);
    conv<32, 32, 4, 128, 4>(A,  nbr2,  N2, W32 + 5 * S32, BN32(6), X2, 0, T);  // t2
    concat(B, T, N2, 32, CAT);
    conv<64, 32, 8, 64, 4>(CAT, nbr2, N2, W6432 + 1 * S6432, BN32(12), 0, CAT, A);

    // ---- up to level 1 ----
    conv<32, 32, 4, 128, 4>(A,  nbri2, N1, W32 + 6 * S32, BN32(7), 0, 0, B);   // xu2
    conv<32, 32, 4, 128, 4>(X1, nbr1,  N1, W32 + 7 * S32, BN32(8), 0, 0, A);
    conv<32, 32, 4, 128, 4>(A,  nbr1,  N1, W32 + 8 * S32, BN32(9), X1, 0, T);  // t1
    concat(B, T, N1, 32, CAT);
    conv<64, 32, 8, 64, 4>(CAT, nbr1, N1, W6432 + 2 * S6432, BN32(13), 0, CAT, A);

    // ---- head ----
    conv<32, 32, 4, 128, 4>(A, nbr1, N1, W32 + 9 * S32, BN32(10), 0, 0, OUT);

#undef BN32
#undef BN64
}